// round 16
// baseline (speedup 1.0000x reference)
#include <cuda_runtime.h>
#include <cuda_pipeline.h>
#include <math.h>

#define D_ 1024
#define H_ 8
#define F_ 4096
#define TILE_ 32     // rows per filter block
#define SR 4         // rows per score stage
#define SCHUNK 256   // floats per row-chunk per stage (1KB)
#define NSTG 3       // pipeline stages per warp
#define STG_FLOATS (SR * SCHUNK)   // 4KB per stage
#define SWARPS 16    // warps per score block

// Scratch
__device__ unsigned long long g_keys[8 * 4096 * 8];   // [b][f][h]
__device__ float g_mask[64 * 4096];                   // [bh][f]
__device__ int   g_ctr;                               // work-stealing counter

__device__ __forceinline__ unsigned int f2ord(float f) {
    unsigned int u = __float_as_uint(f);
    return (u & 0x80000000u) ? ~u : (u | 0x80000000u);
}
__device__ __forceinline__ unsigned long long pack2(float lo, float hi) {
    unsigned long long p;
    asm("mov.b64 %0, {%1, %2};" : "=l"(p) : "f"(lo), "f"(hi));
    return p;
}
__device__ __forceinline__ void unpack2(unsigned long long p, float& lo, float& hi) {
    asm("mov.b64 {%0, %1}, %2;" : "=f"(lo), "=f"(hi) : "l"(p));
}
__device__ __forceinline__ unsigned long long shfl_xor64(unsigned long long v, int off) {
    unsigned int lo = __shfl_xor_sync(0xffffffffu, (unsigned int)v, off);
    unsigned int hi = __shfl_xor_sync(0xffffffffu, (unsigned int)(v >> 32), off);
    return ((unsigned long long)hi << 32) | lo;
}
#define FMA2(acc, a, b) \
    asm("fma.rn.f32x2 %0, %1, %2, %0;" : "+l"(acc) : "l"(a), "l"(b))
#define ADD2(acc, a) \
    asm("add.rn.f32x2 %0, %0, %1;" : "+l"(acc) : "l"(a))

__device__ __forceinline__ void issue_stage(
    const float* __restrict__ x, float* dst,
    int batch, int c, int lane)
{
    const float* src = x + (size_t)batch * SR * D_ + c * SCHUNK;
#pragma unroll
    for (int r = 0; r < SR; r++)
#pragma unroll
        for (int q = 0; q < 2; q++)
            __pipeline_memcpy_async(dst + r * SCHUNK + (lane + 32 * q) * 4,
                                    src + (size_t)r * D_ + (lane + 32 * q) * 4, 16);
}

__device__ __forceinline__ int steal(int lane, int nbatch) {
    int v = 0;
    if (lane == 0) v = atomicAdd(&g_ctr, 1);
    v = __shfl_sync(0xffffffffu, v, 0);
    return (v < nbatch) ? v : -1;
}

// ---------------------------------------------------------------------------
// Kernel 1: 16 warps/SM, warp-private cp.async 3-stage pipeline with atomic
// work-stealing (perfect balance at any warp count). Pipeline crosses batch
// boundaries: while computing chunk c, chunk c+2 (possibly of the next stolen
// batch) is issued. No syncs in the main loop (lane-owns-column staging).
// ---------------------------------------------------------------------------
__global__ void __launch_bounds__(512, 1) score_kernel(
    const float* __restrict__ x,
    const float* __restrict__ W,      // [D, H]
    const float* __restrict__ bias,   // [H]
    int nrows)
{
    extern __shared__ float smem[];
    float* Wt  = smem;                          // 32KB
    float* stg = smem + H_ * D_;                // 16 warps * 3 * 4KB = 192KB

    const int tid  = threadIdx.x;
    const int warp = tid >> 5;
    const int lane = tid & 31;

    for (int i = tid; i < D_ * H_; i += 512) {
        int d = i >> 3, h = i & 7;
        Wt[h * D_ + d] = W[i];
    }
    __syncthreads();

    const int j0 = __brev((unsigned)lane) >> 27;
    const int h0 = j0 & 7;
    const int rA = j0 >> 3;
    const float bias_h = bias[h0];

    const int nbatch = nrows / SR;
    float* buf = stg + warp * NSTG * STG_FLOATS;
    const unsigned long long ABS2 = 0x7FFFFFFF7FFFFFFFull;

    int cur = steal(lane, nbatch);
    if (cur < 0) return;                 // no later __syncthreads -> safe

    // prologue: chunks 0,1 of cur into slots 0,1
    issue_stage(x, buf + 0 * STG_FLOATS, cur, 0, lane);
    __pipeline_commit();
    issue_stage(x, buf + 1 * STG_FLOATS, cur, 1, lane);
    __pipeline_commit();

    unsigned long long acc[32];
    int mglob = 0;

    while (cur >= 0) {
        int nxt = -2;                    // not yet stolen

#pragma unroll
        for (int j = 0; j < 32; j++) acc[j] = 0ull;

#pragma unroll
        for (int c = 0; c < 4; c++) {
            // issue chunk c+2 (crosses into the next batch at c>=2)
            {
                const int ca = c + 2;
                int ib, cc;
                if (ca < 4) { ib = cur; cc = ca; }
                else {
                    if (nxt == -2) nxt = steal(lane, nbatch);
                    ib = nxt; cc = ca - 4;
                }
                if (ib >= 0)
                    issue_stage(x, buf + ((mglob + 2) % NSTG) * STG_FLOATS,
                                ib, cc, lane);
                __pipeline_commit();
            }
            __pipeline_wait_prior(2);    // chunk c of cur is resident

            const float4* bp = (const float4*)(buf + (mglob % NSTG) * STG_FLOATS);
#pragma unroll
            for (int j2 = 0; j2 < 2; j2++) {
                const int d4l = lane + 32 * j2;
                unsigned long long axy[SR], azw[SR];
#pragma unroll
                for (int r = 0; r < SR; r++) {
                    float4 v = bp[r * (SCHUNK / 4) + d4l];
                    axy[r] = pack2(v.x, v.y) & ABS2;
                    azw[r] = pack2(v.z, v.w) & ABS2;
                }
                const int dg = c * SCHUNK + 4 * d4l;
#pragma unroll
                for (int h = 0; h < H_; h++) {
                    const ulonglong2 wv = *(const ulonglong2*)&Wt[h * D_ + dg];
#pragma unroll
                    for (int r = 0; r < SR; r++) {
                        FMA2(acc[r * 8 + h], axy[r], wv.x);
                        FMA2(acc[r * 8 + h], azw[r], wv.y);
                    }
                }
            }
            mglob++;
        }

        // tree reduce: 32 values -> 1 per lane
        {
            int n = 32;
#pragma unroll
            for (int off = 16; off >= 1; off >>= 1) {
#pragma unroll
                for (int i = 0; i < 16; i++) {
                    if (i < n / 2) {
                        unsigned long long xx = acc[2 * i], yy = acc[2 * i + 1];
                        unsigned long long t = (lane & off) ? xx : yy;
                        t = shfl_xor64(t, off);
                        unsigned long long keep = (lane & off) ? yy : xx;
                        ADD2(keep, t);
                        acc[i] = keep;
                    }
                }
                n >>= 1;
            }
            const int row = cur * SR + rA;
            float lo, hi;
            unpack2(acc[0], lo, hi);
            float s = lo + hi + bias_h;
            const int b = row / F_;
            const int f = row - b * F_;
            const unsigned int finv = 0xFFFFFFFFu - (unsigned int)f;
            g_keys[(size_t)row * H_ + h0] =
                ((unsigned long long)f2ord(s) << 32) | (unsigned long long)finv;
        }

        cur = (nxt == -2) ? steal(lane, nbatch) : nxt;
        // on entry to next batch, its chunks 0,1 are already in flight
    }
}

// ---------------------------------------------------------------------------
// Kernel 2: per (b,h) exact radix-select with early exit (unique-bin key is
// the k-th largest; expected after ~2-3 passes). Writes mask scratch [bh][f].
// ---------------------------------------------------------------------------
__global__ void __launch_bounds__(1024) topk_kernel(
    const float* __restrict__ sparsity_offset)
{
    __shared__ unsigned long long s[F_];   // 32 KB
    __shared__ int hist[4][256];
    __shared__ int sh_bin, sh_need, sh_c;
    __shared__ unsigned long long sh_thr;

    const int bh = blockIdx.x;
    const int b  = bh >> 3;
    const int h  = bh & (H_ - 1);
    const int t  = threadIdx.x;
    const int lane = t & 31;
    const int wg4 = (t >> 5) & 3;

#pragma unroll
    for (int j = 0; j < 4; j++) {
        int i = t + j * 1024;
        s[i] = g_keys[((size_t)b * F_ + i) * H_ + h];
    }

    if (t == 0) {
        double off = (double)sparsity_offset[h];
        double sp  = 1.0 / (1.0 + exp(-off)) * 0.3 + 0.15;
        int k = (int)((double)F_ * sp);     // trunc, matches numpy int()
        if (k < 1)  k = 1;
        if (k > F_) k = F_;
        sh_need = k;
    }
    __syncthreads();

    unsigned long long prefix = 0ull, pmask = 0ull;

    for (int shift = 56; shift >= 0; shift -= 8) {
        if (t < 256) { hist[0][t] = 0; hist[1][t] = 0; hist[2][t] = 0; hist[3][t] = 0; }
        __syncthreads();
#pragma unroll
        for (int j = 0; j < 4; j++) {
            unsigned long long key = s[t + j * 1024];
            if ((key & pmask) == prefix)
                atomicAdd(&hist[wg4][(int)((key >> shift) & 255ull)], 1);
        }
        __syncthreads();

        if (t < 32) {
            int c[8], lsum = 0;
#pragma unroll
            for (int q = 0; q < 8; q++) {
                int bin = lane * 8 + q;
                c[q] = hist[0][bin] + hist[1][bin] + hist[2][bin] + hist[3][bin];
                lsum += c[q];
            }
            int ssum = lsum;
#pragma unroll
            for (int off = 1; off < 32; off <<= 1) {
                int o = __shfl_down_sync(0xffffffffu, ssum, off);
                if (lane + off < 32) ssum += o;
            }
            int above = ssum - lsum;
            int need = sh_need;
            int cum = above;
#pragma unroll
            for (int q = 7; q >= 0; q--) {
                int bin = lane * 8 + q;
                if (cum < need && need <= cum + c[q]) {
                    sh_bin = bin;
                    sh_need = need - cum;
                    sh_c = c[q];
                }
                cum += c[q];
            }
        }
        __syncthreads();
        prefix |= ((unsigned long long)sh_bin) << shift;
        pmask  |= (255ull << shift);

        if (sh_c == 1) {
#pragma unroll
            for (int j = 0; j < 4; j++) {
                unsigned long long key = s[t + j * 1024];
                if ((key & pmask) == prefix) sh_thr = key;
            }
            __syncthreads();
            break;
        }
        __syncthreads();
    }

    const unsigned long long thr = sh_thr;   // exact k-th largest key
#pragma unroll
    for (int j = 0; j < 4; j++) {
        int i = t + j * 1024;
        g_mask[(size_t)bh * F_ + i] = (s[i] >= thr) ? 1.0f : 0.0f;
    }
}

// ---------------------------------------------------------------------------
// Kernel 3: dense filter, ballot-partitioned (round-15; measured win).
// ---------------------------------------------------------------------------
__global__ void __launch_bounds__(256) filter_kernel(
    const float* __restrict__ x,
    float* __restrict__ xout,
    float* __restrict__ mask_out)     // may be null
{
    __shared__ float m[TILE_][H_];
    const int tile0 = blockIdx.x * TILE_;
    const int b = tile0 >> 12;                    // F_ = 4096
    const int f0 = tile0 & (F_ - 1);
    const int t = threadIdx.x;
    const int head = t >> 5;
    const int lane = t & 31;

    m[lane][head] = g_mask[((size_t)(b * H_ + head)) * F_ + f0 + lane];
    __syncthreads();

    if (mask_out)
        mask_out[(size_t)tile0 * H_ + t] = m[t >> 3][t & 7];

    const bool kept = (m[lane][head] != 0.0f);
    const unsigned bits = __ballot_sync(0xffffffffu, kept);

    const size_t base = (size_t)tile0 * D_ + head * 128 + lane * 4;

    unsigned kb = bits;
    while (kb) {
        int r0 = -1, r1 = -1, r2 = -1, r3 = -1;
        r0 = __ffs(kb) - 1; kb &= kb - 1;
        if (kb) { r1 = __ffs(kb) - 1; kb &= kb - 1; }
        if (kb) { r2 = __ffs(kb) - 1; kb &= kb - 1; }
        if (kb) { r3 = __ffs(kb) - 1; kb &= kb - 1; }
        float4 v0, v1, v2, v3;
        v0 = __ldcs((const float4*)(x + base + (size_t)r0 * D_));
        if (r1 >= 0) v1 = __ldcs((const float4*)(x + base + (size_t)r1 * D_));
        if (r2 >= 0) v2 = __ldcs((const float4*)(x + base + (size_t)r2 * D_));
        if (r3 >= 0) v3 = __ldcs((const float4*)(x + base + (size_t)r3 * D_));
        __stcs((float4*)(xout + base + (size_t)r0 * D_), v0);
        if (r1 >= 0) __stcs((float4*)(xout + base + (size_t)r1 * D_), v1);
        if (r2 >= 0) __stcs((float4*)(xout + base + (size_t)r2 * D_), v2);
        if (r3 >= 0) __stcs((float4*)(xout + base + (size_t)r3 * D_), v3);
    }

    const float4 z4 = make_float4(0.f, 0.f, 0.f, 0.f);
    unsigned zb = ~bits;
    while (zb) {
        int r0 = __ffs(zb) - 1; zb &= zb - 1;
        __stcs((float4*)(xout + base + (size_t)r0 * D_), z4);
    }
}

// ---------------------------------------------------------------------------
extern "C" void kernel_launch(void* const* d_in, const int* in_sizes, int n_in,
                              void* d_out, int out_size)
{
    const float* x    = (const float*)d_in[0];  // (B,F,D)
    const float* W    = (const float*)d_in[1];  // (D,H)
    const float* bias = (const float*)d_in[2];  // (H)
    const float* soff = (const float*)d_in[3];  // (H)

    const int nrows = in_sizes[0] / D_;         // B*F
    const int B = nrows / F_;

    float* xout = (float*)d_out;
    float* mask_out = nullptr;
    long long need = (long long)nrows * D_ + (long long)nrows * H_;
    if ((long long)out_size >= need)
        mask_out = (float*)d_out + (size_t)nrows * D_;

    const int smem_bytes = (H_ * D_ + SWARPS * NSTG * STG_FLOATS) * sizeof(float); // 224KB
    static int attr_set = 0;
    static void* ctr_addr = nullptr;
    if (!attr_set) {
        cudaFuncSetAttribute(score_kernel,
                             cudaFuncAttributeMaxDynamicSharedMemorySize, smem_bytes);
        cudaGetSymbolAddress(&ctr_addr, g_ctr);
        attr_set = 1;
    }

    // 0) reset work-stealing counter (graph-capturable memset node)
    cudaMemsetAsync(ctr_addr, 0, sizeof(int));
    // 1) scores -> keys (16 warps/SM, stealing pipeline)
    score_kernel<<<148, 512, smem_bytes>>>(x, W, bias, nrows);
    // 2) exact top-k with early-exit radix + mask scratch
    topk_kernel<<<B * H_, 1024>>>(soff);
    // 3) dense filter, ballot-partitioned, mask folded in
    filter_kernel<<<nrows / TILE_, 256>>>(x, xout, mask_out);
}

// round 17
// speedup vs baseline: 1.0356x; 1.0356x over previous
#include <cuda_runtime.h>
#include <cuda_pipeline.h>
#include <math.h>

#define D_ 1024
#define H_ 8
#define F_ 4096
#define TILE_ 64     // rows per filter block (512 threads, 2 warps per head)
#define SR 4         // rows per score stage
#define SCHUNK 256   // floats per row-chunk per stage (1KB)
#define NSTG 6       // pipeline stages per warp
#define STG_FLOATS (SR * SCHUNK)   // 4KB per stage

// Scratch
__device__ unsigned long long g_keys[8 * 4096 * 8];   // [b][f][h]
__device__ float g_mask[64 * 4096];                   // [bh][f]

__device__ __forceinline__ unsigned int f2ord(float f) {
    unsigned int u = __float_as_uint(f);
    return (u & 0x80000000u) ? ~u : (u | 0x80000000u);
}
__device__ __forceinline__ unsigned long long pack2(float lo, float hi) {
    unsigned long long p;
    asm("mov.b64 %0, {%1, %2};" : "=l"(p) : "f"(lo), "f"(hi));
    return p;
}
__device__ __forceinline__ void unpack2(unsigned long long p, float& lo, float& hi) {
    asm("mov.b64 {%0, %1}, %2;" : "=f"(lo), "=f"(hi) : "l"(p));
}
__device__ __forceinline__ unsigned long long shfl_xor64(unsigned long long v, int off) {
    unsigned int lo = __shfl_xor_sync(0xffffffffu, (unsigned int)v, off);
    unsigned int hi = __shfl_xor_sync(0xffffffffu, (unsigned int)(v >> 32), off);
    return ((unsigned long long)hi << 32) | lo;
}
#define FMA2(acc, a, b) \
    asm("fma.rn.f32x2 %0, %1, %2, %0;" : "+l"(acc) : "l"(a), "l"(b))
#define ADD2(acc, a) \
    asm("add.rn.f32x2 %0, %0, %1;" : "+l"(acc) : "l"(a))

__device__ __forceinline__ void issue_stage(
    const float* __restrict__ x, float* dst,
    int batch, int c, int lane)
{
    const float* src = x + (size_t)batch * SR * D_ + c * SCHUNK;
#pragma unroll
    for (int r = 0; r < SR; r++)
#pragma unroll
        for (int q = 0; q < 2; q++)
            __pipeline_memcpy_async(dst + r * SCHUNK + (lane + 32 * q) * 4,
                                    src + (size_t)r * D_ + (lane + 32 * q) * 4, 16);
}

// ---------------------------------------------------------------------------
// Kernel 1: round-11/15 score (best measured: 28.7-30.2us). 8 warps/SM,
// warp-private cp.async 6-stage pipeline, static interleaved distribution,
// no syncs in the main loop (lane-owns-column staging).
// ---------------------------------------------------------------------------
__global__ void __launch_bounds__(256, 1) score_kernel(
    const float* __restrict__ x,
    const float* __restrict__ W,      // [D, H]
    const float* __restrict__ bias,   // [H]
    int nrows)
{
    extern __shared__ float smem[];
    float* Wt  = smem;                          // 32KB
    float* stg = smem + H_ * D_;                // 8 warps * NSTG * 4KB

    const int tid  = threadIdx.x;
    const int warp = tid >> 5;
    const int lane = tid & 31;
    const int bid  = blockIdx.x;
    const int grid = gridDim.x;

    for (int i = tid; i < D_ * H_; i += 256) {
        int d = i >> 3, h = i & 7;
        Wt[h * D_ + d] = W[i];
    }
    __syncthreads();

    const int j0 = __brev((unsigned)lane) >> 27;
    const int h0 = j0 & 7;
    const int rA = j0 >> 3;
    const float bias_h = bias[h0];

    const int nbatch = nrows / SR;
    const int gw = bid * 8 + warp;
    const int nwarps = grid * 8;
    const int my_n = (nbatch > gw) ? ((nbatch - gw + nwarps - 1) / nwarps) : 0;
    const int total_m = my_n * 4;
    if (total_m == 0) return;

    float* buf = stg + warp * NSTG * STG_FLOATS;
    const unsigned long long ABS2 = 0x7FFFFFFF7FFFFFFFull;

#pragma unroll
    for (int i = 0; i < NSTG - 1; i++) {
        if (i < total_m)
            issue_stage(x, buf + (i % NSTG) * STG_FLOATS,
                        gw + (i >> 2) * nwarps, i & 3, lane);
        __pipeline_commit();
    }

    unsigned long long acc[32];

    for (int m = 0; m < total_m; m++) {
        const int c = m & 3;
        const int batch = gw + (m >> 2) * nwarps;

        {
            const int mi = m + NSTG - 1;
            if (mi < total_m)
                issue_stage(x, buf + (mi % NSTG) * STG_FLOATS,
                            gw + (mi >> 2) * nwarps, mi & 3, lane);
            __pipeline_commit();
        }
        __pipeline_wait_prior(NSTG - 1);

        if (c == 0) {
#pragma unroll
            for (int j = 0; j < 32; j++) acc[j] = 0ull;
        }

        const float4* bp = (const float4*)(buf + (m % NSTG) * STG_FLOATS);
#pragma unroll
        for (int j2 = 0; j2 < 2; j2++) {
            const int d4l = lane + 32 * j2;
            unsigned long long axy[SR], azw[SR];
#pragma unroll
            for (int r = 0; r < SR; r++) {
                float4 v = bp[r * (SCHUNK / 4) + d4l];
                axy[r] = pack2(v.x, v.y) & ABS2;
                azw[r] = pack2(v.z, v.w) & ABS2;
            }
            const int dg = c * SCHUNK + 4 * d4l;
#pragma unroll
            for (int h = 0; h < H_; h++) {
                const ulonglong2 wv = *(const ulonglong2*)&Wt[h * D_ + dg];
#pragma unroll
                for (int r = 0; r < SR; r++) {
                    FMA2(acc[r * 8 + h], axy[r], wv.x);
                    FMA2(acc[r * 8 + h], azw[r], wv.y);
                }
            }
        }

        if (c == 3) {
            int n = 32;
#pragma unroll
            for (int off = 16; off >= 1; off >>= 1) {
#pragma unroll
                for (int i = 0; i < 16; i++) {
                    if (i < n / 2) {
                        unsigned long long xx = acc[2 * i], yy = acc[2 * i + 1];
                        unsigned long long t = (lane & off) ? xx : yy;
                        t = shfl_xor64(t, off);
                        unsigned long long keep = (lane & off) ? yy : xx;
                        ADD2(keep, t);
                        acc[i] = keep;
                    }
                }
                n >>= 1;
            }
            const int row = batch * SR + rA;
            float lo, hi;
            unpack2(acc[0], lo, hi);
            float s = lo + hi + bias_h;
            const int b = row / F_;
            const int f = row - b * F_;
            const unsigned int finv = 0xFFFFFFFFu - (unsigned int)f;
            g_keys[(size_t)row * H_ + h0] =
                ((unsigned long long)f2ord(s) << 32) | (unsigned long long)finv;
        }
    }
}

// ---------------------------------------------------------------------------
// Kernel 2: per (b,h) exact radix-select with early exit (unique-bin key is
// the k-th largest; expected after ~2-3 passes). Writes mask scratch [bh][f].
// ---------------------------------------------------------------------------
__global__ void __launch_bounds__(1024) topk_kernel(
    const float* __restrict__ sparsity_offset)
{
    __shared__ unsigned long long s[F_];   // 32 KB
    __shared__ int hist[4][256];
    __shared__ int sh_bin, sh_need, sh_c;
    __shared__ unsigned long long sh_thr;

    const int bh = blockIdx.x;
    const int b  = bh >> 3;
    const int h  = bh & (H_ - 1);
    const int t  = threadIdx.x;
    const int lane = t & 31;
    const int wg4 = (t >> 5) & 3;

#pragma unroll
    for (int j = 0; j < 4; j++) {
        int i = t + j * 1024;
        s[i] = g_keys[((size_t)b * F_ + i) * H_ + h];
    }

    if (t == 0) {
        double off = (double)sparsity_offset[h];
        double sp  = 1.0 / (1.0 + exp(-off)) * 0.3 + 0.15;
        int k = (int)((double)F_ * sp);     // trunc, matches numpy int()
        if (k < 1)  k = 1;
        if (k > F_) k = F_;
        sh_need = k;
    }
    __syncthreads();

    unsigned long long prefix = 0ull, pmask = 0ull;

    for (int shift = 56; shift >= 0; shift -= 8) {
        if (t < 256) { hist[0][t] = 0; hist[1][t] = 0; hist[2][t] = 0; hist[3][t] = 0; }
        __syncthreads();
#pragma unroll
        for (int j = 0; j < 4; j++) {
            unsigned long long key = s[t + j * 1024];
            if ((key & pmask) == prefix)
                atomicAdd(&hist[wg4][(int)((key >> shift) & 255ull)], 1);
        }
        __syncthreads();

        if (t < 32) {
            int c[8], lsum = 0;
#pragma unroll
            for (int q = 0; q < 8; q++) {
                int bin = lane * 8 + q;
                c[q] = hist[0][bin] + hist[1][bin] + hist[2][bin] + hist[3][bin];
                lsum += c[q];
            }
            int ssum = lsum;
#pragma unroll
            for (int off = 1; off < 32; off <<= 1) {
                int o = __shfl_down_sync(0xffffffffu, ssum, off);
                if (lane + off < 32) ssum += o;
            }
            int above = ssum - lsum;
            int need = sh_need;
            int cum = above;
#pragma unroll
            for (int q = 7; q >= 0; q--) {
                int bin = lane * 8 + q;
                if (cum < need && need <= cum + c[q]) {
                    sh_bin = bin;
                    sh_need = need - cum;
                    sh_c = c[q];
                }
                cum += c[q];
            }
        }
        __syncthreads();
        prefix |= ((unsigned long long)sh_bin) << shift;
        pmask  |= (255ull << shift);

        if (sh_c == 1) {
#pragma unroll
            for (int j = 0; j < 4; j++) {
                unsigned long long key = s[t + j * 1024];
                if ((key & pmask) == prefix) sh_thr = key;
            }
            __syncthreads();
            break;
        }
        __syncthreads();
    }

    const unsigned long long thr = sh_thr;   // exact k-th largest key
#pragma unroll
    for (int j = 0; j < 4; j++) {
        int i = t + j * 1024;
        g_mask[(size_t)bh * F_ + i] = (s[i] >= thr) ? 1.0f : 0.0f;
    }
}

// ---------------------------------------------------------------------------
// Kernel 3: dense filter, ballot-partitioned, 64-row tiles / 512 threads
// (2 warps per head). Kept rows copied in batches of 8 (MLP=8); zero rows
// pure streaming stores. Mask output folded in.
// ---------------------------------------------------------------------------
__global__ void __launch_bounds__(512) filter_kernel(
    const float* __restrict__ x,
    float* __restrict__ xout,
    float* __restrict__ mask_out)     // may be null
{
    __shared__ float m[TILE_][H_];
    const int tile0 = blockIdx.x * TILE_;
    const int b = tile0 >> 12;                    // F_ = 4096
    const int f0 = tile0 & (F_ - 1);
    const int t = threadIdx.x;
    const int warp = t >> 5;
    const int lane = t & 31;
    const int head = warp >> 1;                   // 2 warps per head
    const int rbase = (warp & 1) * 32;            // row sub-tile 0..31 / 32..63

    {   // coalesced mask tile load: head hd = t>>6, f-offset = t&63
        const int hd = t >> 6;
        const int fi = t & 63;
        m[fi][hd] = g_mask[((size_t)(b * H_ + hd)) * F_ + f0 + fi];
    }
    __syncthreads();

    if (mask_out)   // coalesced 2KB: row = t>>3, head = t&7
        mask_out[(size_t)tile0 * H_ + t] = m[t >> 3][t & 7];

    const bool kept = (m[rbase + lane][head] != 0.0f);   // lane indexes row
    const unsigned bits = __ballot_sync(0xffffffffu, kept);

    const size_t base = (size_t)(tile0 + rbase) * D_ + head * 128 + lane * 4;

    // kept rows: batches of 8 independent load+store
    unsigned kb = bits;
    while (kb) {
        int rr[8];
        float4 vv[8];
        int nb = 0;
#pragma unroll
        for (int s = 0; s < 8; s++) {
            rr[s] = -1;
            if (kb) { rr[s] = __ffs(kb) - 1; kb &= kb - 1; nb = s + 1; }
        }
#pragma unroll
        for (int s = 0; s < 8; s++)
            if (rr[s] >= 0)
                vv[s] = __ldcs((const float4*)(x + base + (size_t)rr[s] * D_));
#pragma unroll
        for (int s = 0; s < 8; s++)
            if (rr[s] >= 0)
                __stcs((float4*)(xout + base + (size_t)rr[s] * D_), vv[s]);
        (void)nb;
    }

    // zero rows: pure streaming stores
    const float4 z4 = make_float4(0.f, 0.f, 0.f, 0.f);
    unsigned zb = ~bits;
    while (zb) {
        int r0 = __ffs(zb) - 1; zb &= zb - 1;
        __stcs((float4*)(xout + base + (size_t)r0 * D_), z4);
    }
}

// ---------------------------------------------------------------------------
extern "C" void kernel_launch(void* const* d_in, const int* in_sizes, int n_in,
                              void* d_out, int out_size)
{
    const float* x    = (const float*)d_in[0];  // (B,F,D)
    const float* W    = (const float*)d_in[1];  // (D,H)
    const float* bias = (const float*)d_in[2];  // (H)
    const float* soff = (const float*)d_in[3];  // (H)

    const int nrows = in_sizes[0] / D_;         // B*F
    const int B = nrows / F_;

    float* xout = (float*)d_out;
    float* mask_out = nullptr;
    long long need = (long long)nrows * D_ + (long long)nrows * H_;
    if ((long long)out_size >= need)
        mask_out = (float*)d_out + (size_t)nrows * D_;

    const int smem_bytes = (H_ * D_ + 8 * NSTG * STG_FLOATS) * sizeof(float); // 224KB
    static int attr_set = 0;
    if (!attr_set) {
        cudaFuncSetAttribute(score_kernel,
                             cudaFuncAttributeMaxDynamicSharedMemorySize, smem_bytes);
        attr_set = 1;
    }

    // 1) scores -> keys (round-11/15 pipeline; best measured)
    score_kernel<<<148, 256, smem_bytes>>>(x, W, bias, nrows);
    // 2) exact top-k with early-exit radix + mask scratch
    topk_kernel<<<B * H_, 1024>>>(soff);
    // 3) dense filter, ballot-partitioned, 64-row tiles
    filter_kernel<<<nrows / TILE_, 512>>>(x, xout, mask_out);
}